// round 1
// baseline (speedup 1.0000x reference)
#include <cuda_runtime.h>
#include <math.h>

#define C        144
#define W        77
#define KW       10
#define FC       64
#define CONV_OUT 68            // W - KW + 1
#define CONCAT   (C*FC + CONV_OUT)   // 9284
#define H2       128

// Scratch (no device allocation allowed)
__device__ __align__(16) float g_concat[CONCAT];
__device__ float g_acc = 0.0f;
__device__ unsigned int g_cnt = 0u;

__device__ __forceinline__ float warp_reduce(float v) {
#pragma unroll
    for (int o = 16; o > 0; o >>= 1) v += __shfl_down_sync(0xffffffffu, v, o);
    return v;
}

// ---------------------------------------------------------------------------
// stage1: blocks 0..143 -> per-channel Linear(77,64); block 144 -> conv
// ---------------------------------------------------------------------------
__global__ __launch_bounds__(256) void stage1_kernel(
    const float* __restrict__ x,       // [C, W]
    const float* __restrict__ fc_w,    // [C, FC, W]
    const float* __restrict__ fc_b,    // [C, FC]
    const float* __restrict__ conv_w,  // [C, KW]
    const float* __restrict__ conv_b)  // [1]
{
    const int tid  = threadIdx.x;
    const int lane = tid & 31;
    const int warp = tid >> 5;
    const int c    = blockIdx.x;

    if (c < C) {
        // ---- per-channel FC: 8 warps x 8 outputs, warp-reduced dots ----
        __shared__ float xs[W];
        if (tid < W) xs[tid] = x[c * W + tid];
        __syncthreads();

#pragma unroll
        for (int i = 0; i < 8; i++) {
            const int d = warp * 8 + i;                 // 0..63
            const float* row = fc_w + (size_t)(c * FC + d) * W;
            float s = row[lane] * xs[lane] + row[lane + 32] * xs[lane + 32];
            if (lane < W - 64)                          // 13 tail elements
                s += row[lane + 64] * xs[lane + 64];
            s = warp_reduce(s);
            if (lane == 0) g_concat[c * FC + d] = s + fc_b[c * FC + d];
        }
    } else {
        // ---- conv block: warps split channels, lanes cover output positions ----
        __shared__ float ws[C * KW];          // 1440 floats
        __shared__ float part[8][CONV_OUT];
        for (int i = tid; i < C * KW; i += 256) ws[i] = conv_w[i];
        __syncthreads();

        float s0 = 0.f, s1 = 0.f, s2 = 0.f;   // outputs lane, lane+32, lane+64
        for (int ch = warp; ch < C; ch += 8) {
            const float* xr = x + ch * W;
#pragma unroll
            for (int k = 0; k < KW; k++) {
                const float wv = ws[ch * KW + k];
                s0 += xr[lane + k]      * wv;
                s1 += xr[lane + 32 + k] * wv;
                if (lane < CONV_OUT - 64)      // 4 tail outputs
                    s2 += xr[lane + 64 + k] * wv;
            }
        }
        part[warp][lane]      = s0;
        part[warp][lane + 32] = s1;
        if (lane < CONV_OUT - 64) part[warp][lane + 64] = s2;
        __syncthreads();

        if (tid < CONV_OUT) {
            float acc = conv_b[0];
#pragma unroll
            for (int wq = 0; wq < 8; wq++) acc += part[wq][tid];
            g_concat[C * FC + tid] = acc;
        }
    }
}

// ---------------------------------------------------------------------------
// stage2: block j computes h[j] = relu(w2[j]·concat + b2[j]); final scalar
// layer fused via last-block reduction (atomic counter + accumulator reset).
// ---------------------------------------------------------------------------
__global__ __launch_bounds__(256) void stage2_kernel(
    const float* __restrict__ w2,   // [H2, CONCAT]
    const float* __restrict__ b2,   // [H2]
    const float* __restrict__ w3,   // [1, H2]
    const float* __restrict__ b3,   // [1]
    float* __restrict__ out)        // [1]
{
    const int j    = blockIdx.x;
    const int tid  = threadIdx.x;
    const int lane = tid & 31;
    const int warp = tid >> 5;

    // rows are 9284 floats = 37136 bytes: 16B aligned, 2321 float4s exactly
    const float4* row = reinterpret_cast<const float4*>(w2 + (size_t)j * CONCAT);
    const float4* cc  = reinterpret_cast<const float4*>(g_concat);

    float s = 0.f;
    for (int i = tid; i < CONCAT / 4; i += 256) {
        const float4 a = row[i];
        const float4 b = cc[i];
        s += a.x * b.x + a.y * b.y + a.z * b.z + a.w * b.w;
    }

    s = warp_reduce(s);
    __shared__ float red[8];
    if (lane == 0) red[warp] = s;
    __syncthreads();

    if (warp == 0) {
        float v = (lane < 8) ? red[lane] : 0.f;
        v = warp_reduce(v);
        if (lane == 0) {
            const float h = fmaxf(v + b2[j], 0.f);
            atomicAdd(&g_acc, h * w3[j]);
            __threadfence();
            const unsigned n = atomicAdd(&g_cnt, 1u);
            if (n == H2 - 1) {
                // last block: read total, reset scratch for next graph replay
                const float total = atomicExch(&g_acc, 0.f);
                g_cnt = 0u;
                const float o2 = fmaxf(total + b3[0], 0.f);
                out[0] = 1.f / (1.f + expf(-o2));
            }
        }
    }
}

// ---------------------------------------------------------------------------
extern "C" void kernel_launch(void* const* d_in, const int* in_sizes, int n_in,
                              void* d_out, int out_size) {
    const float* x      = (const float*)d_in[0];
    const float* fc_w   = (const float*)d_in[1];
    const float* fc_b   = (const float*)d_in[2];
    const float* conv_w = (const float*)d_in[3];
    const float* conv_b = (const float*)d_in[4];
    const float* w2     = (const float*)d_in[5];
    const float* b2     = (const float*)d_in[6];
    const float* w3     = (const float*)d_in[7];
    const float* b3     = (const float*)d_in[8];

    stage1_kernel<<<C + 1, 256>>>(x, fc_w, fc_b, conv_w, conv_b);
    stage2_kernel<<<H2, 256>>>(w2, b2, w3, b3, (float*)d_out);
}

// round 2
// speedup vs baseline: 1.2959x; 1.2959x over previous
#include <cuda_runtime.h>
#include <math.h>

#define C        144
#define W        77
#define KW       10
#define FC       64
#define CONV_OUT 68                    // W - KW + 1
#define CONCAT   (C*FC + CONV_OUT)     // 9284
#define H2       128
#define GRID     148                   // one block per SM -> guaranteed co-resident

// Scratch (no device allocation allowed)
__device__ __align__(16) float g_concat[CONCAT];
__device__ float        g_acc  = 0.0f;
__device__ unsigned int g_cnt  = 0u;   // phase-B finish counter
__device__ unsigned int g_done = 0u;   // phase-A arrival counter

__device__ __forceinline__ float warp_reduce(float v) {
#pragma unroll
    for (int o = 16; o > 0; o >>= 1) v += __shfl_down_sync(0xffffffffu, v, o);
    return v;
}

// ---------------------------------------------------------------------------
// Single fused persistent kernel.
//  Phase A: blocks 0..143 -> per-channel Linear(77,64); block 144 -> conv;
//           blocks 145..147 idle (arrive only).
//  Grid barrier via atomic counter (all 148 blocks resident: 1 per SM).
//  Phase B: blocks 0..127 -> h[j] = relu(w2[j]·concat + b2[j]); final scalar
//           layer fused via last-block reduction; last block resets counters.
// ---------------------------------------------------------------------------
__global__ __launch_bounds__(256, 1) void fused_kernel(
    const float* __restrict__ x,       // [C, W]
    const float* __restrict__ fc_w,    // [C, FC, W]
    const float* __restrict__ fc_b,    // [C, FC]
    const float* __restrict__ conv_w,  // [C, KW]
    const float* __restrict__ conv_b,  // [1]
    const float* __restrict__ w2,      // [H2, CONCAT]
    const float* __restrict__ b2,      // [H2]
    const float* __restrict__ w3,      // [1, H2]
    const float* __restrict__ b3,      // [1]
    float* __restrict__ out)           // [1]
{
    const int tid  = threadIdx.x;
    const int lane = tid & 31;
    const int warp = tid >> 5;
    const int b    = blockIdx.x;

    __shared__ float sh[C * KW];       // reused: xs[] for FC blocks, ws[] for conv
    __shared__ float part[8][CONV_OUT];
    __shared__ float red[8];

    // ------------------------------ Phase A ------------------------------
    if (b < C) {
        // per-channel FC: 8 warps x 8 outputs, warp-reduced dots
        if (tid < W) sh[tid] = x[b * W + tid];
        __syncthreads();

#pragma unroll
        for (int i = 0; i < 8; i++) {
            const int d = warp * 8 + i;                 // 0..63
            const float* row = fc_w + (size_t)(b * FC + d) * W;
            float s = row[lane] * sh[lane] + row[lane + 32] * sh[lane + 32];
            if (lane < W - 64)                          // 13 tail elements
                s += row[lane + 64] * sh[lane + 64];
            s = warp_reduce(s);
            if (lane == 0) g_concat[b * FC + d] = s + fc_b[b * FC + d];
        }
    } else if (b == C) {
        // conv block: warps split channels, lanes cover output positions
        for (int i = tid; i < C * KW; i += 256) sh[i] = conv_w[i];
        __syncthreads();

        float s0 = 0.f, s1 = 0.f, s2 = 0.f;   // outputs lane, lane+32, lane+64
        for (int ch = warp; ch < C; ch += 8) {
            const float* xr = x + ch * W;
#pragma unroll
            for (int k = 0; k < KW; k++) {
                const float wv = sh[ch * KW + k];
                s0 += xr[lane + k]      * wv;
                s1 += xr[lane + 32 + k] * wv;
                if (lane < CONV_OUT - 64)      // 4 tail outputs
                    s2 += xr[lane + 64 + k] * wv;
            }
        }
        part[warp][lane]      = s0;
        part[warp][lane + 32] = s1;
        if (lane < CONV_OUT - 64) part[warp][lane + 64] = s2;
        __syncthreads();

        if (tid < CONV_OUT) {
            float acc = conv_b[0];
#pragma unroll
            for (int wq = 0; wq < 8; wq++) acc += part[wq][tid];
            g_concat[C * FC + tid] = acc;
        }
    }
    // else: blocks 145..147 do no phase-A work

    // --------------------------- grid barrier ----------------------------
    __syncthreads();                    // all block stores to g_concat issued
    if (tid == 0) {
        __threadfence();                // release g_concat writes
        atomicAdd(&g_done, 1u);
        // spin until every block has arrived
        while (atomicAdd(&g_done, 0u) < GRID) { __nanosleep(64); }
    }
    __syncthreads();
    __threadfence();                    // acquire: see all g_concat writes

    // ------------------------------ Phase B ------------------------------
    if (b < H2) {
        const int j = b;
        // rows are 9284 floats = 37136 bytes: 16B aligned, 2321 float4 exactly
        const float4* row = reinterpret_cast<const float4*>(w2 + (size_t)j * CONCAT);
        const float4* cc  = reinterpret_cast<const float4*>(g_concat);

        float s = 0.f;
        // 2321 = 9*256 + 17: 9 fully-unrolled strided iterations (all in range)
#pragma unroll
        for (int k = 0; k < 9; k++) {
            const int i = tid + k * 256;         // max 255 + 2048 = 2303 < 2321
            const float4 a = row[i];
            const float4 c = cc[i];
            s += a.x * c.x + a.y * c.y + a.z * c.z + a.w * c.w;
        }
        if (tid < 17) {                          // tail 2304..2320
            const int i = 2304 + tid;
            const float4 a = row[i];
            const float4 c = cc[i];
            s += a.x * c.x + a.y * c.y + a.z * c.z + a.w * c.w;
        }

        s = warp_reduce(s);
        if (lane == 0) red[warp] = s;
        __syncthreads();

        if (warp == 0) {
            float v = (lane < 8) ? red[lane] : 0.f;
            v = warp_reduce(v);
            if (lane == 0) {
                const float h = fmaxf(v + b2[j], 0.f);
                atomicAdd(&g_acc, h * w3[j]);
                __threadfence();
                const unsigned n = atomicAdd(&g_cnt, 1u);
                if (n == H2 - 1) {
                    // final block: emit output, reset all scratch for replay
                    const float total = atomicExch(&g_acc, 0.f);
                    g_cnt  = 0u;
                    g_done = 0u;
                    const float o2 = fmaxf(total + b3[0], 0.f);
                    out[0] = 1.f / (1.f + expf(-o2));
                }
            }
        }
    }
}

// ---------------------------------------------------------------------------
extern "C" void kernel_launch(void* const* d_in, const int* in_sizes, int n_in,
                              void* d_out, int out_size) {
    const float* x      = (const float*)d_in[0];
    const float* fc_w   = (const float*)d_in[1];
    const float* fc_b   = (const float*)d_in[2];
    const float* conv_w = (const float*)d_in[3];
    const float* conv_b = (const float*)d_in[4];
    const float* w2     = (const float*)d_in[5];
    const float* b2     = (const float*)d_in[6];
    const float* w3     = (const float*)d_in[7];
    const float* b3     = (const float*)d_in[8];

    fused_kernel<<<GRID, 256>>>(x, fc_w, fc_b, conv_w, conv_b,
                                w2, b2, w3, b3, (float*)d_out);
}